// round 1
// baseline (speedup 1.0000x reference)
#include <cuda_runtime.h>
#include <math.h>

// Histogram2D: Gaussian-CDF weighted 2D deposit of 500k points (first two of 6
// phase-space coords) onto a 128x128 grid, then normalize to a density.
//
// Key fact: bandwidth == bin width, so each point's weight vector per axis is
// effectively 11-sparse (erf tail beyond 5 bins < 6e-7). We scatter 11x11
// windows into a per-CTA shared-memory histogram (64KB), merge with global
// atomics, and normalize with a single-block kernel.

#define NB   128           // bins per axis
#define NE   129           // edges per axis
#define HW   5             // window half-width in bins
#define WIN  11            // window width (2*HW+1)
#define HIST_THREADS 256

// ---------------------------------------------------------------------------
__global__ void zero_kernel(float* __restrict__ out) {
    int i = blockIdx.x * blockDim.x + threadIdx.x;
    if (i < NB * NB) out[i] = 0.0f;
}

// ---------------------------------------------------------------------------
__global__ __launch_bounds__(HIST_THREADS)
void hist_kernel(const float* __restrict__ x,
                 const float* __restrict__ ex,
                 const float* __restrict__ ey,
                 float* __restrict__ out,
                 int n)
{
    extern __shared__ float sh[];
    float* shist = sh;                 // NB*NB floats
    float* sex   = sh + NB * NB;       // NE floats
    float* sey   = sex + NE;           // NE floats

    for (int i = threadIdx.x; i < NB * NB; i += blockDim.x) shist[i] = 0.0f;
    for (int i = threadIdx.x; i < NE; i += blockDim.x) {
        sex[i] = ex[i];
        sey[i] = ey[i];
    }
    __syncthreads();

    const float lox = sex[0];
    const float loy = sey[0];
    const float dx  = sex[1] - sex[0];
    const float dy  = sey[1] - sey[0];
    const float inv_dx = 1.0f / dx;
    const float inv_dy = 1.0f / dy;
    // bandwidth = 1.0 * bin width; erf argument scale = 1/(bw*sqrt(2))
    const float invs_x = 1.0f / (dx * 1.4142135623730951f);
    const float invs_y = 1.0f / (dy * 1.4142135623730951f);

    const int stride = gridDim.x * blockDim.x;
    for (int p = blockIdx.x * blockDim.x + threadIdx.x; p < n; p += stride) {
        // x is (n, 6) row-major; we need columns 0 and 1 -> aligned float2.
        float2 u = *reinterpret_cast<const float2*>(x + (size_t)p * 6);

        int cx = (int)floorf((u.x - lox) * inv_dx);
        int cy = (int)floorf((u.y - loy) * inv_dy);

        // Window fully outside grid on either axis -> zero contribution.
        if (cx + HW < 0 || cx - HW > NB - 1) continue;
        if (cy + HW < 0 || cy - HW > NB - 1) continue;

        const int ix0 = cx - HW;
        const int iy0 = cy - HW;

        // Clamped-edge trick: for bins outside [0, NB), both edges clamp to
        // the same boundary edge -> erf difference is EXACTLY zero, so the
        // weight is an exact mask with no extra branching.
        float wx[WIN];
        {
            int e0 = min(max(ix0, 0), NB);
            float prev = erff((sex[e0] - u.x) * invs_x);
            #pragma unroll
            for (int k = 0; k < WIN; k++) {
                int ei = min(max(ix0 + k + 1, 0), NB);
                float cur = erff((sex[ei] - u.x) * invs_x);
                wx[k] = 0.5f * (cur - prev);
                prev = cur;
            }
        }
        float wy[WIN];
        {
            int e0 = min(max(iy0, 0), NB);
            float prev = erff((sey[e0] - u.y) * invs_y);
            #pragma unroll
            for (int k = 0; k < WIN; k++) {
                int ei = min(max(iy0 + k + 1, 0), NB);
                float cur = erff((sey[ei] - u.y) * invs_y);
                wy[k] = 0.5f * (cur - prev);
                prev = cur;
            }
        }

        #pragma unroll
        for (int kx = 0; kx < WIN; kx++) {
            float wv = wx[kx];
            if (wv == 0.0f) continue;           // out-of-range row (exact zero)
            int row = (ix0 + kx) * NB + iy0;
            #pragma unroll
            for (int ky = 0; ky < WIN; ky++) {
                float pw = wv * wy[ky];
                if (pw != 0.0f) atomicAdd(&shist[row + ky], pw);
            }
        }
    }

    __syncthreads();
    for (int i = threadIdx.x; i < NB * NB; i += blockDim.x) {
        float v = shist[i];
        if (v != 0.0f) atomicAdd(&out[i], v);
    }
}

// ---------------------------------------------------------------------------
__global__ void norm_kernel(float* __restrict__ out,
                            const float* __restrict__ ex,
                            const float* __restrict__ ey)
{
    __shared__ float red[512];
    __shared__ float s_scale;

    float s = 0.0f;
    for (int i = threadIdx.x; i < NB * NB; i += blockDim.x) s += out[i];
    red[threadIdx.x] = s;
    __syncthreads();

    for (int off = 256; off > 0; off >>= 1) {
        if (threadIdx.x < off) red[threadIdx.x] += red[threadIdx.x + off];
        __syncthreads();
    }
    if (threadIdx.x == 0) {
        float dx = ex[1] - ex[0];
        float dy = ey[1] - ey[0];
        s_scale = 1.0f / (red[0] * dx * dy);
    }
    __syncthreads();

    float sc = s_scale;
    for (int i = threadIdx.x; i < NB * NB; i += blockDim.x) out[i] *= sc;
}

// ---------------------------------------------------------------------------
extern "C" void kernel_launch(void* const* d_in, const int* in_sizes, int n_in,
                              void* d_out, int out_size)
{
    const float* x  = (const float*)d_in[0];
    const float* ex = (const float*)d_in[1];
    const float* ey = (const float*)d_in[2];
    float* out = (float*)d_out;

    int n = in_sizes[0] / 6;   // number of particles

    // Dynamic smem: NB*NB hist + 2*NE edges (floats).
    const int smem_bytes = (NB * NB + 2 * NE) * (int)sizeof(float);
    cudaFuncSetAttribute(hist_kernel,
                         cudaFuncAttributeMaxDynamicSharedMemorySize,
                         smem_bytes);

    zero_kernel<<<(NB * NB + 255) / 256, 256>>>(out);

    // 3 CTAs/SM * 148 SMs (smem-limited occupancy), grid-stride over points.
    const int nblocks = 444;
    hist_kernel<<<nblocks, HIST_THREADS, smem_bytes>>>(x, ex, ey, out, n);

    norm_kernel<<<1, 512>>>(out, ex, ey);
}

// round 6
// speedup vs baseline: 1.3825x; 1.3825x over previous
#include <cuda_runtime.h>
#include <cstdint>
#include <math.h>

// Histogram2D via bilinear particle-in-cell deposit + exact separable
// erf-CDF convolution.
//
//   hist[i][j] = sum_p Kx(i - posx_p) * Ky(j - posy_p)
//
// K is shift-invariant in continuous position, so: deposit points bilinearly
// onto a fine grid (q=16 cells/bin, padded 8 bins each side), then convolve
// with the sampled kernel table W (exact erf masses at fine-cell centers).
// Only the bilinear deposit approximates (per-tap err <= |K''|/(8 q^2) ~ 1.5e-4,
// mean-zero over frac -> ~1e-5 relative after summing; threshold is 1e-3).

#define NB    128
#define Q     16
#define PAD   128                 // fine cells of padding each side (8 bins)
#define NF    (NB*Q + 2*PAD)      // 2304 fine cells per axis
#define TAP0  40                  // first nonzero tap (t index)
#define NTAP  192                 // taps t in [40, 232)
#define NM    139                 // m-groups of 16 fx covering fx in [40, 2264)

__device__ float g_fg[NF * NF];       // fine grid, 21.2 MB
__device__ float g_B[NF * NB];        // after pass1: B[fy][ix], 1.18 MB
__device__ float g_W[256];            // kernel tap table (bin-unit invariant)
__device__ float g_colsum[NB];        // per-iy column sums from pass2

// ---------------------------------------------------------------------------
// Zero fine grid + B, and compute the tap table W.
__global__ void k_init()
{
    const size_t nf4 = (size_t)(NF * NF) / 4 + (size_t)(NF * NB) / 4;
    float4* fg4 = reinterpret_cast<float4*>(g_fg);   // g_B follows logically
    const float4 z = make_float4(0.f, 0.f, 0.f, 0.f);
    const size_t fg_f4 = (size_t)(NF * NF) / 4;

    size_t i = (size_t)blockIdx.x * blockDim.x + threadIdx.x;
    const size_t stride = (size_t)gridDim.x * blockDim.x;
    for (; i < nf4; i += stride) {
        if (i < fg_f4) fg4[i] = z;
        else reinterpret_cast<float4*>(g_B)[i - fg_f4] = z;
    }

    if (blockIdx.x == 0 && threadIdx.x < 256) {
        int t = threadIdx.x;
        // fine-cell center offset from bin-left-edge, in bin units
        float zc = ((float)t + 0.5f) * (1.0f / (float)Q) - (float)(PAD / Q);
        // Gaussian(center zc, sigma = 1 bin) mass in [0, 1]
        const float is2 = 0.70710678118654752f;
        g_W[t] = 0.5f * (erff((1.0f - zc) * is2) - erff((-zc) * is2));
    }
}

// ---------------------------------------------------------------------------
// Bilinear deposit: 4 RED.F32 per point onto the fine grid.
__global__ __launch_bounds__(256)
void k_deposit(const float* __restrict__ x,
               const float* __restrict__ ex,
               const float* __restrict__ ey,
               int n)
{
    const float lox = ex[0], dx = ex[1] - ex[0];
    const float loy = ey[0], dy = ey[1] - ey[0];
    const float sx = (float)Q / dx;
    const float sy = (float)Q / dy;

    int p = blockIdx.x * blockDim.x + threadIdx.x;
    if (p >= n) return;

    float2 u = *reinterpret_cast<const float2*>(x + (size_t)p * 6);

    float pfx = (u.x - lox) * sx + ((float)PAD - 0.5f);
    float pfy = (u.y - loy) * sy + ((float)PAD - 0.5f);
    float fx0 = floorf(pfx), fy0 = floorf(pfy);
    float a = pfx - fx0, b = pfy - fy0;
    int ix = (int)fx0, iy = (int)fy0;
    if ((unsigned)ix >= NF - 1 || (unsigned)iy >= NF - 1) return;  // <1e-12 mass

    float w11 = a * b;
    float w10 = a - w11;
    float w01 = b - w11;
    float w00 = 1.0f - a - b + w11;

    float* r0 = g_fg + (size_t)ix * NF + iy;
    atomicAdd(r0,          w00);
    atomicAdd(r0 + 1,      w01);
    atomicAdd(r0 + NF,     w10);
    atomicAdd(r0 + NF + 1, w11);
}

// ---------------------------------------------------------------------------
// Pass 1: reduce over fx.  B[fy][ix] = sum_fx W[fx - ix*Q] * FG[fx][fy].
// fx is processed in groups of 16 (m-groups): fx = TAP0 + 16*m + r.
// Each fx contributes exactly 12 taps: ix = m - k, t = TAP0 + r + 16*k, k=0..11.
// Grid: (16 fx-segments of 9 m-groups) x (9 fy-tiles of 256). 144 CTAs.
__global__ __launch_bounds__(256)
void k_pass1()
{
    __shared__ float sW[256];
    sW[threadIdx.x] = g_W[threadIdx.x];
    __syncthreads();

    const int fy = blockIdx.y * 256 + threadIdx.x;
    const int M0 = blockIdx.x * 9;

    float acc[20];                    // ix = (M0-11) .. (M0+8)
    #pragma unroll
    for (int k = 0; k < 20; k++) acc[k] = 0.f;

    #pragma unroll
    for (int r = 0; r < 16; r++) {
        float v[9];
        #pragma unroll
        for (int g = 0; g < 9; g++) {
            int m = M0 + g;
            v[g] = 0.f;
            if (m < NM)
                v[g] = g_fg[(size_t)(TAP0 + 16 * m + r) * NF + fy];
        }
        #pragma unroll
        for (int k = 0; k < 12; k++) {
            float w = sW[TAP0 + r + 16 * k];
            #pragma unroll
            for (int g = 0; g < 9; g++)
                acc[g + 11 - k] += w * v[g];   // slot = (m - k) - (M0 - 11)
        }
    }

    float* brow = g_B + (size_t)fy * NB;
    #pragma unroll
    for (int k = 0; k < 20; k++) {
        int ix = M0 - 11 + k;
        if (ix >= 0 && ix < NB && acc[k] != 0.f)
            atomicAdd(brow + ix, acc[k]);
    }
}

// ---------------------------------------------------------------------------
// Pass 2: reduce over fy.  hist[ix][iy] = sum_t W[t] * B[iy*Q + t][ix].
// Grid: 128 CTAs (iy), 128 threads (ix).
__global__ __launch_bounds__(128)
void k_pass2(float* __restrict__ out)
{
    __shared__ float sW[256];
    sW[threadIdx.x] = g_W[threadIdx.x];
    sW[threadIdx.x + 128] = g_W[threadIdx.x + 128];
    __syncthreads();

    const int iy = blockIdx.x;
    const int ix = threadIdx.x;
    const float* bcol = g_B + (size_t)(iy * Q) * NB + ix;

    float a0 = 0.f, a1 = 0.f, a2 = 0.f, a3 = 0.f;
    #pragma unroll 4
    for (int t = TAP0; t < TAP0 + NTAP; t += 4) {
        a0 += sW[t + 0] * bcol[(size_t)(t + 0) * NB];
        a1 += sW[t + 1] * bcol[(size_t)(t + 1) * NB];
        a2 += sW[t + 2] * bcol[(size_t)(t + 2) * NB];
        a3 += sW[t + 3] * bcol[(size_t)(t + 3) * NB];
    }
    float acc = (a0 + a1) + (a2 + a3);

    out[(size_t)ix * NB + iy] = acc;

    __shared__ float red[128];
    red[ix] = acc;
    __syncthreads();
    #pragma unroll
    for (int off = 64; off > 0; off >>= 1) {
        if (ix < off) red[ix] += red[ix + off];
        __syncthreads();
    }
    if (ix == 0) g_colsum[iy] = red[0];
}

// ---------------------------------------------------------------------------
__global__ void k_norm(float* __restrict__ out,
                       const float* __restrict__ ex,
                       const float* __restrict__ ey)
{
    __shared__ float red[256];
    __shared__ float s_scale;
    float s = (threadIdx.x < NB) ? g_colsum[threadIdx.x] : 0.0f;
    red[threadIdx.x] = s;
    __syncthreads();
    #pragma unroll
    for (int off = 128; off > 0; off >>= 1) {
        if (threadIdx.x < off) red[threadIdx.x] += red[threadIdx.x + off];
        __syncthreads();
    }
    if (threadIdx.x == 0) {
        float dx = ex[1] - ex[0];
        float dy = ey[1] - ey[0];
        s_scale = 1.0f / (red[0] * dx * dy);
    }
    __syncthreads();
    float sc = s_scale;
    for (int i = threadIdx.x; i < NB * NB; i += blockDim.x) out[i] *= sc;
}

// ---------------------------------------------------------------------------
extern "C" void kernel_launch(void* const* d_in, const int* in_sizes, int n_in,
                              void* d_out, int out_size)
{
    const float* x  = (const float*)d_in[0];
    const float* ex = (const float*)d_in[1];
    const float* ey = (const float*)d_in[2];
    float* out = (float*)d_out;

    int n = in_sizes[0] / 6;

    k_init<<<1024, 256>>>();
    k_deposit<<<(n + 255) / 256, 256>>>(x, ex, ey, n);
    k_pass1<<<dim3(16, 9), 256>>>();
    k_pass2<<<NB, NB>>>(out);
    k_norm<<<1, 256>>>(out, ex, ey);
}

// round 7
// speedup vs baseline: 3.0771x; 2.2257x over previous
#include <cuda_runtime.h>
#include <cstdint>
#include <math.h>

// Histogram2D via bilinear particle-in-cell deposit + exact separable
// erf-CDF convolution, q=8 fine cells per bin.
//
//   hist[i][j] = sum_p Kx(i - posx_p) * Ky(j - posy_p)
//
// Deposit points bilinearly onto a padded fine grid (q=8 cells/bin, 8 bins of
// padding), then convolve with the sampled kernel table W (exact erf masses at
// fine-cell centers): pass1 reduces fx -> Bt[ix][fy] (transposed for pass2
// locality), pass2 reduces fy via a smem-staged row, then normalize.
// Only the bilinear deposit approximates: error ~ 1/q^2, measured 1.3e-5 at
// q=16 -> ~5e-5 at q=8 (threshold 1e-3).

#define NB    128
#define Q     8
#define PADB  8                   // padding in bins
#define PAD   (PADB*Q)            // 64 fine cells
#define NF    (NB*Q + 2*PAD)      // 1152 fine cells per axis
#define TAP0  20                  // first tap (zc ~ -5.4 bins)
#define NTAP  96                  // taps t in [20, 116): 12-bin support
#define NM    139                 // m-groups of 8 fx
#define MSEG  14                  // m-groups per pass1 CTA
#define NSEG  10                  // ceil(NM/MSEG)

__device__ float g_fg[NF * NF];       // fine grid [fx][fy], 5.3 MB
__device__ float g_Bt[NB * NF];       // after pass1: Bt[ix][fy], 590 KB
__device__ float g_W[128];            // kernel tap table

// ---------------------------------------------------------------------------
// Zero fine grid + Bt, compute tap table W.
__global__ void k_init()
{
    const size_t fg_f4  = (size_t)(NF * NF) / 4;
    const size_t tot_f4 = fg_f4 + (size_t)(NB * NF) / 4;
    const float4 z = make_float4(0.f, 0.f, 0.f, 0.f);

    size_t i = (size_t)blockIdx.x * blockDim.x + threadIdx.x;
    const size_t stride = (size_t)gridDim.x * blockDim.x;
    for (; i < tot_f4; i += stride) {
        if (i < fg_f4) reinterpret_cast<float4*>(g_fg)[i] = z;
        else           reinterpret_cast<float4*>(g_Bt)[i - fg_f4] = z;
    }

    if (blockIdx.x == 0 && threadIdx.x < 128) {
        int t = threadIdx.x;
        // fine-cell center offset from bin-left-edge, in bin units
        float zc = ((float)t + 0.5f) * (1.0f / (float)Q) - (float)PADB;
        const float is2 = 0.70710678118654752f;  // 1/sqrt(2), sigma = 1 bin
        g_W[t] = 0.5f * (erff((1.0f - zc) * is2) - erff((-zc) * is2));
    }
}

// ---------------------------------------------------------------------------
// Bilinear deposit: 4 RED.F32 per point onto the fine grid.
__global__ __launch_bounds__(256)
void k_deposit(const float* __restrict__ x,
               const float* __restrict__ ex,
               const float* __restrict__ ey,
               int n)
{
    const float lox = ex[0], dx = ex[1] - ex[0];
    const float loy = ey[0], dy = ey[1] - ey[0];
    const float sx = (float)Q / dx;
    const float sy = (float)Q / dy;

    int p = blockIdx.x * blockDim.x + threadIdx.x;
    if (p >= n) return;

    float2 u = *reinterpret_cast<const float2*>(x + (size_t)p * 6);

    float pfx = (u.x - lox) * sx + ((float)PAD - 0.5f);
    float pfy = (u.y - loy) * sy + ((float)PAD - 0.5f);
    float fx0 = floorf(pfx), fy0 = floorf(pfy);
    float a = pfx - fx0, b = pfy - fy0;
    int ix = (int)fx0, iy = (int)fy0;
    if ((unsigned)ix >= NF - 1 || (unsigned)iy >= NF - 1) return;  // negligible mass

    float w11 = a * b;
    float w10 = a - w11;
    float w01 = b - w11;
    float w00 = 1.0f - a - b + w11;

    float* r0 = g_fg + (size_t)ix * NF + iy;
    atomicAdd(r0,          w00);
    atomicAdd(r0 + 1,      w01);
    atomicAdd(r0 + NF,     w10);
    atomicAdd(r0 + NF + 1, w11);
}

// ---------------------------------------------------------------------------
// Pass 1: reduce over fx.  Bt[ix][fy] = sum_fx W[fx - ix*Q] * FG[fx][fy].
// fx = TAP0 + 8*m + r; each fx hits 12 bins: ix = m - k, t = TAP0 + r + 8k.
// Grid: (NSEG m-segments of MSEG) x (9 fy-tiles of 128). 90 CTAs.
__global__ __launch_bounds__(128)
void k_pass1()
{
    __shared__ float sW[128];
    sW[threadIdx.x] = g_W[threadIdx.x];
    __syncthreads();

    const int fy = blockIdx.y * 128 + threadIdx.x;
    const int M0 = blockIdx.x * MSEG;

    float acc[MSEG + 11];                 // ix = (M0-11) .. (M0+MSEG-1)
    #pragma unroll
    for (int s = 0; s < MSEG + 11; s++) acc[s] = 0.f;

    #pragma unroll
    for (int r = 0; r < Q; r++) {
        float v[MSEG];
        #pragma unroll
        for (int g = 0; g < MSEG; g++) {
            int m = M0 + g;
            v[g] = (m < NM) ? g_fg[(size_t)(TAP0 + Q * m + r) * NF + fy] : 0.f;
        }
        #pragma unroll
        for (int k = 0; k < 12; k++) {
            float w = sW[TAP0 + r + Q * k];
            #pragma unroll
            for (int g = 0; g < MSEG; g++)
                acc[g + 11 - k] += w * v[g];      // slot = (m-k) - (M0-11)
        }
    }

    // Coalesced (consecutive-fy) atomic merge of segment-boundary overlaps.
    #pragma unroll
    for (int s = 0; s < MSEG + 11; s++) {
        int ix = M0 - 11 + s;
        if (ix >= 0 && ix < NB && acc[s] != 0.f)
            atomicAdd(&g_Bt[(size_t)ix * NF + fy], acc[s]);
    }
}

// ---------------------------------------------------------------------------
// Pass 2: reduce over fy.  hist[ix][iy] = sum_t W[t] * Bt[ix][iy*Q + t].
// One CTA per ix; stage the 4.6KB Bt row into padded smem (conflict-free),
// then each thread (iy) does 96 LDS+FFMA.
#define SPAD(i) ((i) + ((i) >> 3))            // pad 1 float per 8 -> lanes hit 9*iy banks
__global__ __launch_bounds__(128)
void k_pass2(float* __restrict__ out)
{
    __shared__ float sW[128];
    __shared__ float sB[NF + NF / 8];
    sW[threadIdx.x] = g_W[threadIdx.x];

    const int ix = blockIdx.x;
    const int iy = threadIdx.x;
    const float* brow = g_Bt + (size_t)ix * NF;
    #pragma unroll
    for (int i = iy; i < NF; i += 128) sB[SPAD(i)] = brow[i];
    __syncthreads();

    const int base = iy * Q;
    float a0 = 0.f, a1 = 0.f, a2 = 0.f, a3 = 0.f;
    #pragma unroll
    for (int t = TAP0; t < TAP0 + NTAP; t += 4) {
        a0 += sW[t + 0] * sB[SPAD(base + t + 0)];
        a1 += sW[t + 1] * sB[SPAD(base + t + 1)];
        a2 += sW[t + 2] * sB[SPAD(base + t + 2)];
        a3 += sW[t + 3] * sB[SPAD(base + t + 3)];
    }
    out[(size_t)ix * NB + iy] = (a0 + a1) + (a2 + a3);
}

// ---------------------------------------------------------------------------
// Normalize: hist /= (sum * dx * dy).
__global__ __launch_bounds__(256)
void k_norm(float* __restrict__ out,
            const float* __restrict__ ex,
            const float* __restrict__ ey)
{
    __shared__ float red[256];
    __shared__ float s_scale;

    float s = 0.f;
    for (int i = threadIdx.x; i < NB * NB; i += 256) s += out[i];
    red[threadIdx.x] = s;
    __syncthreads();
    #pragma unroll
    for (int off = 128; off > 0; off >>= 1) {
        if (threadIdx.x < off) red[threadIdx.x] += red[threadIdx.x + off];
        __syncthreads();
    }
    if (threadIdx.x == 0) {
        float dx = ex[1] - ex[0];
        float dy = ey[1] - ey[0];
        s_scale = 1.0f / (red[0] * dx * dy);
    }
    __syncthreads();
    float sc = s_scale;
    for (int i = threadIdx.x; i < NB * NB; i += 256) out[i] *= sc;
}

// ---------------------------------------------------------------------------
extern "C" void kernel_launch(void* const* d_in, const int* in_sizes, int n_in,
                              void* d_out, int out_size)
{
    const float* x  = (const float*)d_in[0];
    const float* ex = (const float*)d_in[1];
    const float* ey = (const float*)d_in[2];
    float* out = (float*)d_out;

    int n = in_sizes[0] / 6;

    k_init<<<512, 256>>>();
    k_deposit<<<(n + 255) / 256, 256>>>(x, ex, ey, n);
    k_pass1<<<dim3(NSEG, 9), 128>>>();
    k_pass2<<<NB, 128>>>(out);
    k_norm<<<1, 256>>>(out, ex, ey);
}